// round 10
// baseline (speedup 1.0000x reference)
#include <cuda_runtime.h>
#include <cstdint>

#define Bb 8
#define Hh 8
#define Nq 1024
#define Cc 256
#define HD 64
#define BH (Bb*Hh)

// ---------------- scratch (device globals; no allocation allowed) ----------
__device__ float g_Qb[BH*Nq*HD];   // [b][h][n][d]  16MB
__device__ float g_Kb[BH*Nq*HD];   // [b][h][n][d]  16MB (holds 1/16 scale after norm)
__device__ float g_red_s[128];
__device__ float g_red_q[128];

// ---------------- f32x2 helpers --------------------------------------------
__device__ __forceinline__ unsigned long long splat_f32(float x){
    unsigned long long r;
    asm("mov.b64 %0, {%1, %1};" : "=l"(r) : "f"(x));
    return r;
}
__device__ __forceinline__ void ffma2(unsigned long long &d,
                                      unsigned long long a,
                                      unsigned long long b){
    asm("fma.rn.f32x2 %0, %1, %2, %0;" : "+l"(d) : "l"(a), "l"(b));
}
__device__ __forceinline__ float2 unpack2(unsigned long long v){
    float2 r;
    asm("mov.b64 {%0, %1}, %2;" : "=f"(r.x), "=f"(r.y) : "l"(v));
    return r;
}

// ---------------- 1) projection GEMM  q,k = x @ W^T ------------------------
__global__ __launch_bounds__(256) void proj_kernel(const float* __restrict__ x,
                                                   const float* __restrict__ qw,
                                                   const float* __restrict__ kw){
    __shared__ float Ast[16][68];
    __shared__ float Bst[16][68];
    const int tid = threadIdx.x;
    const int tx = tid & 15, ty = tid >> 4;
    const int bm = blockIdx.y * 64;
    const int cb = blockIdx.x;            // 0..15 (64-col slab == one head chunk)
    const float* Wp = (cb < 8) ? (qw + (size_t)cb*64*Cc) : (kw + (size_t)(cb-8)*64*Cc);
    float* outbuf = (cb < 8) ? g_Qb : g_Kb;
    const int hsel = cb & 7;

    unsigned long long acc[4][2];
    #pragma unroll
    for (int i=0;i<4;i++){ acc[i][0]=0ull; acc[i][1]=0ull; }

    const int row_ld = tid >> 2;          // 0..63
    const int kq = tid & 3;               // 0..3

    for (int kc = 0; kc < 16; kc++){
        const int k0 = kc*16;
        float4 a4 = *reinterpret_cast<const float4*>(x  + (size_t)(bm + row_ld)*Cc + k0 + kq*4);
        float4 b4 = *reinterpret_cast<const float4*>(Wp + (size_t)row_ld*Cc        + k0 + kq*4);
        Ast[kq*4+0][row_ld]=a4.x; Ast[kq*4+1][row_ld]=a4.y;
        Ast[kq*4+2][row_ld]=a4.z; Ast[kq*4+3][row_ld]=a4.w;
        Bst[kq*4+0][row_ld]=b4.x; Bst[kq*4+1][row_ld]=b4.y;
        Bst[kq*4+2][row_ld]=b4.z; Bst[kq*4+3][row_ld]=b4.w;
        __syncthreads();
        #pragma unroll
        for (int k=0;k<16;k++){
            float4 av = *reinterpret_cast<const float4*>(&Ast[k][ty*4]);
            const unsigned long long* bpp =
                reinterpret_cast<const unsigned long long*>(&Bst[k][tx*4]);
            unsigned long long bp0 = bpp[0], bp1 = bpp[1];
            float avv[4] = {av.x, av.y, av.z, av.w};
            #pragma unroll
            for (int i=0;i<4;i++){
                unsigned long long ap = splat_f32(avv[i]);
                ffma2(acc[i][0], ap, bp0);
                ffma2(acc[i][1], ap, bp1);
            }
        }
        __syncthreads();
    }
    #pragma unroll
    for (int i=0;i<4;i++){
        const int m = bm + ty*4 + i;
        const int b = m >> 10, n = m & 1023;
        float2 p0 = unpack2(acc[i][0]);
        float2 p1 = unpack2(acc[i][1]);
        float4 o = make_float4(p0.x, p0.y, p1.x, p1.y);
        float* dst = outbuf + (((size_t)(b*Hh + hsel))*Nq + n)*HD + tx*4;
        *reinterpret_cast<float4*>(dst) = o;
    }
}

// ---------------- 2) BN stats ----------------------------------------------
__global__ __launch_bounds__(256) void stats_kernel(){
    __shared__ float ss[256], sq[256];
    const int t = blockIdx.x >> 6;
    const int idx = blockIdx.x & 63;
    const float* base = (t ? g_Kb : g_Qb) + (size_t)idx * 65536;
    const float4* b4p = reinterpret_cast<const float4*>(base);
    float s = 0.f, q = 0.f;
    for (int i = threadIdx.x; i < 16384; i += 256){
        float4 v = b4p[i];
        s += (v.x + v.y) + (v.z + v.w);
        q += v.x*v.x + v.y*v.y + v.z*v.z + v.w*v.w;
    }
    ss[threadIdx.x] = s; sq[threadIdx.x] = q;
    __syncthreads();
    for (int o = 128; o > 0; o >>= 1){
        if (threadIdx.x < o){
            ss[threadIdx.x] += ss[threadIdx.x+o];
            sq[threadIdx.x] += sq[threadIdx.x+o];
        }
        __syncthreads();
    }
    if (threadIdx.x == 0){ g_red_s[blockIdx.x] = ss[0]; g_red_q[blockIdx.x] = sq[0]; }
}

// ---------------- 3) BN finalize (redundant per block) + affine + L2 norm --
// K additionally scaled by 1/16 (= 1/sqrt(256) score scale).
__global__ __launch_bounds__(256) void norm_kernel(const float* __restrict__ bnw,
                                                   const float* __restrict__ bnb){
    __shared__ float s_bnp[2][8][2];
    const int tid = threadIdx.x;
    if (tid < 16){
        const int t = tid >> 3, h = tid & 7;
        float S = 0.f, Q = 0.f;
        #pragma unroll
        for (int b = 0; b < 8; b++){
            const int j = t*64 + b*8 + h;
            S += g_red_s[j]; Q += g_red_q[j];
        }
        const float inv = 1.0f / 524288.0f;
        const float mean = S * inv;
        const float var  = Q * inv - mean*mean;
        const float sc = bnw[h] * rsqrtf(var + 1e-5f);
        const float sh = bnb[h] - mean * sc;
        s_bnp[t][h][0] = sc; s_bnp[t][h][1] = sh;
    }
    __syncthreads();

    const int w = tid >> 5, l = tid & 31;
    const int row = blockIdx.x*8 + w;             // 0..131071
    const int t  = row >> 16;
    const int r2 = row & 65535;                   // (b*8+h)*1024 + n
    const int h  = (r2 >> 10) & 7;
    float* base = (t ? g_Kb : g_Qb) + (size_t)r2 * 64;
    float2 v = reinterpret_cast<float2*>(base)[l];
    const float sc = s_bnp[t][h][0], sf = s_bnp[t][h][1];
    v.x = fmaf(v.x, sc, sf);
    v.y = fmaf(v.y, sc, sf);
    float ssum = v.x*v.x + v.y*v.y;
    #pragma unroll
    for (int o = 16; o > 0; o >>= 1) ssum += __shfl_xor_sync(0xffffffffu, ssum, o);
    float nrm = fmaxf(sqrtf(ssum), 1e-12f);
    const float r = (t ? 0.0625f : 1.0f) / nrm;
    v.x *= r; v.y *= r;
    reinterpret_cast<float2*>(base)[l] = v;
}

// ---------------- 4) fused scores GEMM + sparsemax(axis=n) + store ---------
// CTA = (m-tile 32, bh), 1024 threads (32 warps -> 2x latency hiding vs R9).
// Thread tile 4m x 8n (16 f32x2 accs = 32 regs; <=64 regs/thread so the full
// 64K RF supports 32 warps). tm = w&7 (warp-uniform m-group: K LDS are
// broadcasts), tn = (w>>3)*32 + l. Q staged with even-stride swizzle
// word(n) = n + 2*(n>>3). Epilogue: conflict-free transpose to stg, then
// warp-owned sparsemax (warp w owns column w; shuffle butterfly, no CTA
// barriers), writeback + proven coalesced store.
#define QROW 1280                          /* floats per swizzled 1024-n row */
#define QBUF (8*QROW)                      /* floats per d-chunk buffer      */
#define SOFF_QST  0                        /* 2 x 40960B = 81920             */
#define SOFF_KD   81920                    /* float2[64][32] = 16384         */
#define SOFF_STG  0                        /* overlay: float[1024][33] = 135168 */
#define ATTN_SMEM 135168

__global__ __launch_bounds__(1024, 1) void attn_kernel(float* __restrict__ out){
    extern __shared__ char smem[];
    float*  qst   = reinterpret_cast<float*>(smem + SOFF_QST);
    float2* kd    = reinterpret_cast<float2*>(smem + SOFF_KD);
    float*  stg   = reinterpret_cast<float*>(smem + SOFF_STG);

    const int tid = threadIdx.x;
    const int w = tid >> 5, l = tid & 31;
    const int tm = w & 7;                  // warp-uniform m-group (4 m each)
    const int tn = (w >> 3)*32 + l;        // 0..127 n-group (8 n each)
    const int bh = blockIdx.y;
    const int m0 = blockIdx.x * 32;

    const float* Qg = g_Qb + (size_t)bh * Nq * 64;
    const float* Kg = g_Kb + (size_t)bh * Nq * 64;

    // ---- K staging: kd[d][m] = {K[m][d], K[m][d]} (dup for f32x2) ---------
    {
        const int m = tid & 31, dq = tid >> 5;     // dq 0..31, 2 d per thread
        float2 kv = *reinterpret_cast<const float2*>(Kg + (size_t)(m0 + m)*64 + dq*2);
        kd[(dq*2+0)*32 + m] = make_float2(kv.x, kv.x);
        kd[(dq*2+1)*32 + m] = make_float2(kv.y, kv.y);
    }
    // ---- Q chunk 0 -> buffer 0 (even-stride swizzled scalar rows) ---------
    const int n0 = tid;                        // one n-row per thread
    const int w0 = n0 + 2*(n0 >> 3);
    {
        float4 a0 = *reinterpret_cast<const float4*>(Qg + (size_t)n0*64);
        float4 a1 = *reinterpret_cast<const float4*>(Qg + (size_t)n0*64 + 4);
        qst[0*QROW+w0]=a0.x; qst[1*QROW+w0]=a0.y; qst[2*QROW+w0]=a0.z; qst[3*QROW+w0]=a0.w;
        qst[4*QROW+w0]=a1.x; qst[5*QROW+w0]=a1.y; qst[6*QROW+w0]=a1.z; qst[7*QROW+w0]=a1.w;
    }
    __syncthreads();

    unsigned long long acc[4][4];
    #pragma unroll
    for (int mi = 0; mi < 4; mi++)
        #pragma unroll
        for (int nj = 0; nj < 4; nj++) acc[mi][nj] = 0ull;

    const int qb = 10*tn;    // swizzled base word of this thread's 8-n group

    for (int c = 0; c < 8; c++){
        const int buf = c & 1;
        float4 p0, p1;
        if (c < 7){
            const int d0 = (c+1)*8;
            p0 = *reinterpret_cast<const float4*>(Qg + (size_t)n0*64 + d0);
            p1 = *reinterpret_cast<const float4*>(Qg + (size_t)n0*64 + d0 + 4);
        }
        const float* qbase = qst + buf*QBUF;
        #pragma unroll
        for (int dd = 0; dd < 8; dd++){
            const int d = c*8 + dd;
            const ulonglong2* kr =
                reinterpret_cast<const ulonglong2*>(kd + d*32 + tm*4);
            ulonglong2 k01 = kr[0], k23 = kr[1];
            const float* qrow = qbase + dd*QROW + qb;
            unsigned long long qpv[4];
            #pragma unroll
            for (int nj = 0; nj < 4; nj++)
                qpv[nj] = *reinterpret_cast<const unsigned long long*>(qrow + 2*nj);
            unsigned long long kp[4] = {k01.x, k01.y, k23.x, k23.y};
            #pragma unroll
            for (int mi = 0; mi < 4; mi++){
                #pragma unroll
                for (int nj = 0; nj < 4; nj++)
                    ffma2(acc[mi][nj], kp[mi], qpv[nj]);
            }
        }
        if (c < 7){
            float* dstb = qst + (buf^1)*QBUF;
            dstb[0*QROW+w0]=p0.x; dstb[1*QROW+w0]=p0.y; dstb[2*QROW+w0]=p0.z; dstb[3*QROW+w0]=p0.w;
            dstb[4*QROW+w0]=p1.x; dstb[5*QROW+w0]=p1.y; dstb[6*QROW+w0]=p1.z; dstb[7*QROW+w0]=p1.w;
        }
        __syncthreads();
    }

    // ---- transpose scores into staging (overlays dead Q/K smem) -----------
    // stg[r][mloc], r = (n&7)*128 + (n>>3); n = 8*tn + 2*nj (+1), mloc = tm*4+mi
    #pragma unroll
    for (int mi = 0; mi < 4; mi++){
        #pragma unroll
        for (int nj = 0; nj < 4; nj++){
            float2 p = unpack2(acc[mi][nj]);
            const int r0 = (2*nj+0)*128 + tn;
            const int r1 = (2*nj+1)*128 + tn;
            stg[r0*33 + tm*4 + mi] = p.x;
            stg[r1*33 + tm*4 + mi] = p.y;
        }
    }
    __syncthreads();

    // ---- warp-owned sparsemax: warp w owns column w ------------------------
    // lane l reads rows j*32+l (banks (l + w) mod 32: conflict-free).
    float z[32];
    #pragma unroll
    for (int j = 0; j < 32; j++) z[j] = stg[(j*32 + l)*33 + w];

    float tau = -1.0f;
    for (int iter = 0; iter < 48; iter++){
        float s = 0.f, cc = 0.f;
        #pragma unroll
        for (int j = 0; j < 32; j++){
            if (z[j] > tau){ s += z[j]; cc += 1.0f; }
        }
        #pragma unroll
        for (int o = 16; o > 0; o >>= 1){
            s  += __shfl_xor_sync(0xffffffffu, s, o);
            cc += __shfl_xor_sync(0xffffffffu, cc, o);
        }
        const float prev = tau;
        tau = (cc > 0.f) ? (s - 1.0f)/cc : tau;
        if (tau == prev) break;   // warp-uniform
    }

    // ---- write converged results (ReLU) back to stg ------------------------
    #pragma unroll
    for (int j = 0; j < 32; j++){
        float v = z[j] - tau;
        stg[(j*32 + l)*33 + w] = v > 0.f ? v : 0.f;
    }
    __syncthreads();

    // ---- coalesced store: lane spans m, out[b][n][h*1024 + m0 + l] --------
    const int b = bh >> 3, h = bh & 7;
    const size_t obase = (size_t)b*8388608 + (size_t)h*1024 + m0 + l;
    #pragma unroll
    for (int i = 0; i < 32; i++){
        const int r = w*32 + i;
        const int n = ((r & 127) << 3) + (r >> 7);
        out[obase + (size_t)n*8192] = stg[r*33 + l];
    }
}

// ---------------- launcher --------------------------------------------------
extern "C" void kernel_launch(void* const* d_in, const int* in_sizes, int n_in,
                              void* d_out, int out_size){
    const float* x   = (const float*)d_in[0];
    const float* qw  = (const float*)d_in[1];
    const float* kw  = (const float*)d_in[2];
    const float* bnw = (const float*)d_in[3];
    const float* bnb = (const float*)d_in[4];
    float* out = (float*)d_out;
    (void)in_sizes; (void)n_in; (void)out_size;

    cudaFuncSetAttribute(attn_kernel,
                         cudaFuncAttributeMaxDynamicSharedMemorySize, ATTN_SMEM);

    proj_kernel<<<dim3(16, 128), 256>>>(x, qw, kw);
    stats_kernel<<<128, 256>>>();
    norm_kernel<<<16384, 256>>>(bnw, bnb);
    attn_kernel<<<dim3(32, 64), 1024, ATTN_SMEM>>>(out);
}

// round 11
// speedup vs baseline: 1.1776x; 1.1776x over previous
#include <cuda_runtime.h>
#include <cstdint>

#define Bb 8
#define Hh 8
#define Nq 1024
#define Cc 256
#define HD 64
#define BH (Bb*Hh)

// ---------------- scratch (device globals; no allocation allowed) ----------
__device__ float g_Qb[BH*Nq*HD];   // [b][h][n][d] post-proj Q
__device__ float g_Kb[BH*Nq*HD];   // [b][h][n][d] K (1/16 folded after norm)
__device__ float g_Qt[BH*HD*Nq];   // [b][h][d][n] post-norm Q, d-major
__device__ float g_red_s[128];
__device__ float g_red_q[128];

// ---------------- helpers ---------------------------------------------------
__device__ __forceinline__ unsigned long long splat_f32(float x){
    unsigned long long r;
    asm("mov.b64 %0, {%1, %1};" : "=l"(r) : "f"(x));
    return r;
}
__device__ __forceinline__ void ffma2(unsigned long long &d,
                                      unsigned long long a,
                                      unsigned long long b){
    asm("fma.rn.f32x2 %0, %1, %2, %0;" : "+l"(d) : "l"(a), "l"(b));
}
__device__ __forceinline__ float2 unpack2(unsigned long long v){
    float2 r;
    asm("mov.b64 {%0, %1}, %2;" : "=f"(r.x), "=f"(r.y) : "l"(v));
    return r;
}
__device__ __forceinline__ uint32_t smem_u32(const void* p){
    uint32_t a;
    asm("{ .reg .u64 t; cvta.to.shared.u64 t, %1; cvt.u32.u64 %0, t; }"
        : "=r"(a) : "l"(p));
    return a;
}
__device__ __forceinline__ void cp_async8(uint32_t dst, const float* src){
    asm volatile("cp.async.ca.shared.global [%0], [%1], 8;"
                 :: "r"(dst), "l"(src) : "memory");
}
__device__ __forceinline__ void cp_commit(){
    asm volatile("cp.async.commit_group;" ::: "memory");
}
__device__ __forceinline__ void cp_wait1(){
    asm volatile("cp.async.wait_group 1;" ::: "memory");
}
__device__ __forceinline__ void cp_wait0(){
    asm volatile("cp.async.wait_group 0;" ::: "memory");
}

// ---------------- 1) projection GEMM  q,k = x @ W^T ------------------------
__global__ __launch_bounds__(256) void proj_kernel(const float* __restrict__ x,
                                                   const float* __restrict__ qw,
                                                   const float* __restrict__ kw){
    __shared__ float Ast[16][68];
    __shared__ float Bst[16][68];
    const int tid = threadIdx.x;
    const int tx = tid & 15, ty = tid >> 4;
    const int bm = blockIdx.y * 64;
    const int cb = blockIdx.x;
    const float* Wp = (cb < 8) ? (qw + (size_t)cb*64*Cc) : (kw + (size_t)(cb-8)*64*Cc);
    float* outbuf = (cb < 8) ? g_Qb : g_Kb;
    const int hsel = cb & 7;

    unsigned long long acc[4][2];
    #pragma unroll
    for (int i=0;i<4;i++){ acc[i][0]=0ull; acc[i][1]=0ull; }

    const int row_ld = tid >> 2;
    const int kq = tid & 3;

    for (int kc = 0; kc < 16; kc++){
        const int k0 = kc*16;
        float4 a4 = *reinterpret_cast<const float4*>(x  + (size_t)(bm + row_ld)*Cc + k0 + kq*4);
        float4 b4 = *reinterpret_cast<const float4*>(Wp + (size_t)row_ld*Cc        + k0 + kq*4);
        Ast[kq*4+0][row_ld]=a4.x; Ast[kq*4+1][row_ld]=a4.y;
        Ast[kq*4+2][row_ld]=a4.z; Ast[kq*4+3][row_ld]=a4.w;
        Bst[kq*4+0][row_ld]=b4.x; Bst[kq*4+1][row_ld]=b4.y;
        Bst[kq*4+2][row_ld]=b4.z; Bst[kq*4+3][row_ld]=b4.w;
        __syncthreads();
        #pragma unroll
        for (int k=0;k<16;k++){
            float4 av = *reinterpret_cast<const float4*>(&Ast[k][ty*4]);
            const unsigned long long* bpp =
                reinterpret_cast<const unsigned long long*>(&Bst[k][tx*4]);
            unsigned long long bp0 = bpp[0], bp1 = bpp[1];
            float avv[4] = {av.x, av.y, av.z, av.w};
            #pragma unroll
            for (int i=0;i<4;i++){
                unsigned long long ap = splat_f32(avv[i]);
                ffma2(acc[i][0], ap, bp0);
                ffma2(acc[i][1], ap, bp1);
            }
        }
        __syncthreads();
    }
    #pragma unroll
    for (int i=0;i<4;i++){
        const int m = bm + ty*4 + i;
        const int b = m >> 10, n = m & 1023;
        float2 p0 = unpack2(acc[i][0]);
        float2 p1 = unpack2(acc[i][1]);
        float4 o = make_float4(p0.x, p0.y, p1.x, p1.y);
        float* dst = outbuf + (((size_t)(b*Hh + hsel))*Nq + n)*HD + tx*4;
        *reinterpret_cast<float4*>(dst) = o;
    }
}

// ---------------- 2) BN stats ----------------------------------------------
__global__ __launch_bounds__(256) void stats_kernel(){
    __shared__ float ss[256], sq[256];
    const int t = blockIdx.x >> 6;
    const int idx = blockIdx.x & 63;
    const float* base = (t ? g_Kb : g_Qb) + (size_t)idx * 65536;
    const float4* b4p = reinterpret_cast<const float4*>(base);
    float s = 0.f, q = 0.f;
    for (int i = threadIdx.x; i < 16384; i += 256){
        float4 v = b4p[i];
        s += (v.x + v.y) + (v.z + v.w);
        q += v.x*v.x + v.y*v.y + v.z*v.z + v.w*v.w;
    }
    ss[threadIdx.x] = s; sq[threadIdx.x] = q;
    __syncthreads();
    for (int o = 128; o > 0; o >>= 1){
        if (threadIdx.x < o){
            ss[threadIdx.x] += ss[threadIdx.x+o];
            sq[threadIdx.x] += sq[threadIdx.x+o];
        }
        __syncthreads();
    }
    if (threadIdx.x == 0){ g_red_s[blockIdx.x] = ss[0]; g_red_q[blockIdx.x] = sq[0]; }
}

// ---------------- 3) BN finalize + affine + L2 norm -------------------------
// Blocks [0,8192): K in place (1/16 folded). Blocks [8192,8704): Q normalized
// and written TRANSPOSED to g_Qt[bh][d][n] via an smem tile.
__global__ __launch_bounds__(256) void norm_kernel(const float* __restrict__ bnw,
                                                   const float* __restrict__ bnb){
    __shared__ float s_bnp[2][8][2];
    __shared__ float T[64*129];                 // Q-path transpose tile (33KB)
    const int tid = threadIdx.x;
    if (tid < 16){
        const int t = tid >> 3, h = tid & 7;
        float S = 0.f, Q = 0.f;
        #pragma unroll
        for (int b = 0; b < 8; b++){
            const int j = t*64 + b*8 + h;
            S += g_red_s[j]; Q += g_red_q[j];
        }
        const float inv = 1.0f / 524288.0f;
        const float mean = S * inv;
        const float var  = Q * inv - mean*mean;
        const float sc = bnw[h] * rsqrtf(var + 1e-5f);
        const float sh = bnb[h] - mean * sc;
        s_bnp[t][h][0] = sc; s_bnp[t][h][1] = sh;
    }
    __syncthreads();

    const int w = tid >> 5, l = tid & 31;
    if (blockIdx.x < 8192){
        // ---- K path: 8 rows per CTA, in place --------------------------------
        const int r2 = blockIdx.x*8 + w;          // 0..65535 = bh*1024 + n
        const int h  = (r2 >> 10) & 7;
        float* base = g_Kb + (size_t)r2 * 64;
        float2 v = reinterpret_cast<float2*>(base)[l];
        const float sc = s_bnp[1][h][0], sf = s_bnp[1][h][1];
        v.x = fmaf(v.x, sc, sf);
        v.y = fmaf(v.y, sc, sf);
        float ssum = v.x*v.x + v.y*v.y;
        #pragma unroll
        for (int o = 16; o > 0; o >>= 1) ssum += __shfl_xor_sync(0xffffffffu, ssum, o);
        const float r = 0.0625f / fmaxf(sqrtf(ssum), 1e-12f);
        v.x *= r; v.y *= r;
        reinterpret_cast<float2*>(base)[l] = v;
    } else {
        // ---- Q path: 128-row block, normalize + transpose -------------------
        const int qi = blockIdx.x - 8192;         // 0..511
        const int bh = qi >> 3;
        const int n0 = (qi & 7) * 128;
        const int h  = bh & 7;
        const float sc = s_bnp[0][h][0], sf = s_bnp[0][h][1];
        const float* src = g_Qb + ((size_t)bh*1024 + n0) * 64;
        #pragma unroll
        for (int it = 0; it < 16; it++){
            const int rl = w*16 + it;             // 0..127 local row
            float2 v = reinterpret_cast<const float2*>(src + (size_t)rl*64)[l];
            float x = fmaf(v.x, sc, sf);
            float y = fmaf(v.y, sc, sf);
            float ssum = x*x + y*y;
            #pragma unroll
            for (int o = 16; o > 0; o >>= 1) ssum += __shfl_xor_sync(0xffffffffu, ssum, o);
            const float r = 1.0f / fmaxf(sqrtf(ssum), 1e-12f);
            T[(2*l  )*129 + rl] = x * r;
            T[(2*l+1)*129 + rl] = y * r;
        }
        __syncthreads();
        const int d = tid >> 2, c = tid & 3;      // 64 d x 4 column chunks
        float* dst = g_Qt + ((size_t)bh*64 + d)*1024 + n0 + c*32;
        #pragma unroll
        for (int k = 0; k < 8; k++){
            float4 o;
            o.x = T[d*129 + c*32 + 4*k + 0];
            o.y = T[d*129 + c*32 + 4*k + 1];
            o.z = T[d*129 + c*32 + 4*k + 2];
            o.w = T[d*129 + c*32 + 4*k + 3];
            *reinterpret_cast<float4*>(dst + 4*k) = o;
        }
    }
}

// ---------------- 4) fused scores GEMM + sparsemax(axis=n) + store ---------
// CTA = (m-tile 32, bh), 512 threads. Thread tile 8m x 8n (R7 crossbar-optimal
// shape: 4-way Q redundancy). tm = w&3 (warp-uniform m-group), tn = (w>>2)*32+l.
// Q staged from g_Qt (d-major) via cp.async 8B into swizzled rows
// word(n) = n + 2*(n>>3) — no register round-trip, no STS pass, no spills.
// Epilogue: conflict-free transpose to stg, warp-owned sparsemax (2 cols/warp,
// shuffle butterfly), writeback + coalesced store.
#define QROW 1280
#define QBUF (8*QROW)
#define SOFF_KD   81920                    /* float2[64][32] = 16384           */
#define SOFF_STG  0                        /* overlay: float[1024][33]=135168  */
#define ATTN_SMEM 135168

__global__ __launch_bounds__(512, 1) void attn_kernel(float* __restrict__ out){
    extern __shared__ char smem[];
    float*  qst = reinterpret_cast<float*>(smem);
    float2* kd  = reinterpret_cast<float2*>(smem + SOFF_KD);
    float*  stg = reinterpret_cast<float*>(smem + SOFF_STG);
    const uint32_t sb = smem_u32(smem);

    const int tid = threadIdx.x;
    const int w = tid >> 5, l = tid & 31;
    const int tm = w & 3;                  // warp-uniform m-group (8 m each)
    const int tn = (w >> 2)*32 + l;        // 0..127 n-group (8 n each)
    const int bh = blockIdx.y;
    const int m0 = blockIdx.x * 32;

    const float* Qt = g_Qt + (size_t)bh * 65536;     // [d][n]
    const float* Kg = g_Kb + (size_t)bh * 65536;     // [n][d]

    // ---- K staging: kd[d][m] = {K[m][d], K[m][d]} -------------------------
    {
        const int m = tid & 31, dq = tid >> 5;       // dq 0..15
        float4 kv = *reinterpret_cast<const float4*>(Kg + (size_t)(m0 + m)*64 + dq*4);
        kd[(dq*4+0)*32 + m] = make_float2(kv.x, kv.x);
        kd[(dq*4+1)*32 + m] = make_float2(kv.y, kv.y);
        kd[(dq*4+2)*32 + m] = make_float2(kv.z, kv.z);
        kd[(dq*4+3)*32 + m] = make_float2(kv.w, kv.w);
    }

    // ---- cp.async Q chunk staging -----------------------------------------
    const int r_ld = tid >> 6;             // dd-row 0..7
    const int c_ld = tid & 63;             // 64 threads per row
    auto issue_chunk = [&](int ch, int buf){
        const float* srow = Qt + (size_t)(ch*8 + r_ld)*1024 + c_ld*2;
        const uint32_t rowb = sb + 4u*(buf*QBUF + r_ld*QROW);
        #pragma unroll
        for (int j = 0; j < 8; j++){
            const int n  = j*128 + c_ld*2;
            const int wd = n + 2*(n >> 3);
            cp_async8(rowb + 4u*wd, srow + j*128);
        }
    };
    issue_chunk(0, 0);
    cp_commit();

    unsigned long long acc[8][4];
    #pragma unroll
    for (int mi = 0; mi < 8; mi++)
        #pragma unroll
        for (int nj = 0; nj < 4; nj++) acc[mi][nj] = 0ull;

    const int qb = 10*tn;

    for (int c = 0; c < 8; c++){
        if (c < 7){ issue_chunk(c+1, (c+1)&1); cp_commit(); cp_wait1(); }
        else      { cp_wait0(); }
        __syncthreads();
        const float* qbase = qst + (c&1)*QBUF;
        #pragma unroll
        for (int dd = 0; dd < 8; dd++){
            const int d = c*8 + dd;
            const ulonglong2* kr =
                reinterpret_cast<const ulonglong2*>(kd + d*32 + tm*8);
            ulonglong2 k01 = kr[0], k23 = kr[1], k45 = kr[2], k67 = kr[3];
            const float* qrow = qbase + dd*QROW + qb;
            unsigned long long qpv[4];
            #pragma unroll
            for (int nj = 0; nj < 4; nj++)
                qpv[nj] = *reinterpret_cast<const unsigned long long*>(qrow + 2*nj);
            unsigned long long kp[8] = {k01.x,k01.y,k23.x,k23.y,k45.x,k45.y,k67.x,k67.y};
            #pragma unroll
            for (int mi = 0; mi < 8; mi++){
                #pragma unroll
                for (int nj = 0; nj < 4; nj++)
                    ffma2(acc[mi][nj], kp[mi], qpv[nj]);
            }
        }
        __syncthreads();
    }

    // ---- transpose scores into staging ------------------------------------
    #pragma unroll
    for (int mi = 0; mi < 8; mi++){
        #pragma unroll
        for (int nj = 0; nj < 4; nj++){
            float2 p = unpack2(acc[mi][nj]);
            const int r0 = (2*nj+0)*128 + tn;
            const int r1 = (2*nj+1)*128 + tn;
            stg[r0*33 + tm*8 + mi] = p.x;
            stg[r1*33 + tm*8 + mi] = p.y;
        }
    }
    __syncthreads();

    // ---- warp-owned sparsemax: warp w owns columns 2w, 2w+1 ---------------
    const int c0 = 2*w, c1 = 2*w + 1;
    float zA[32], zB[32];
    #pragma unroll
    for (int j = 0; j < 32; j++){
        zA[j] = stg[(j*32 + l)*33 + c0];
        zB[j] = stg[(j*32 + l)*33 + c1];
    }

    float tauA = -1.0f, tauB = -1.0f;
    for (int iter = 0; iter < 48; iter++){
        float sA = 0.f, cA = 0.f, sB = 0.f, cB = 0.f;
        #pragma unroll
        for (int j = 0; j < 32; j++){
            if (zA[j] > tauA){ sA += zA[j]; cA += 1.0f; }
            if (zB[j] > tauB){ sB += zB[j]; cB += 1.0f; }
        }
        #pragma unroll
        for (int o = 16; o > 0; o >>= 1){
            sA += __shfl_xor_sync(0xffffffffu, sA, o);
            cA += __shfl_xor_sync(0xffffffffu, cA, o);
            sB += __shfl_xor_sync(0xffffffffu, sB, o);
            cB += __shfl_xor_sync(0xffffffffu, cB, o);
        }
        const float pA = tauA, pB = tauB;
        tauA = (cA > 0.f) ? (sA - 1.0f)/cA : tauA;
        tauB = (cB > 0.f) ? (sB - 1.0f)/cB : tauB;
        if (tauA == pA && tauB == pB) break;
    }

    #pragma unroll
    for (int j = 0; j < 32; j++){
        float vA = zA[j] - tauA;
        float vB = zB[j] - tauB;
        stg[(j*32 + l)*33 + c0] = vA > 0.f ? vA : 0.f;
        stg[(j*32 + l)*33 + c1] = vB > 0.f ? vB : 0.f;
    }
    __syncthreads();

    // ---- coalesced store ---------------------------------------------------
    const int b = bh >> 3, h = bh & 7;
    const size_t obase = (size_t)b*8388608 + (size_t)h*1024 + m0 + l;
    #pragma unroll
    for (int i = 0; i < 64; i++){
        const int r = w*64 + i;
        const int n = ((r & 127) << 3) + (r >> 7);
        out[obase + (size_t)n*8192] = stg[r*33 + l];
    }
}

// ---------------- launcher --------------------------------------------------
extern "C" void kernel_launch(void* const* d_in, const int* in_sizes, int n_in,
                              void* d_out, int out_size){
    const float* x   = (const float*)d_in[0];
    const float* qw  = (const float*)d_in[1];
    const float* kw  = (const float*)d_in[2];
    const float* bnw = (const float*)d_in[3];
    const float* bnb = (const float*)d_in[4];
    float* out = (float*)d_out;
    (void)in_sizes; (void)n_in; (void)out_size;

    cudaFuncSetAttribute(attn_kernel,
                         cudaFuncAttributeMaxDynamicSharedMemorySize, ATTN_SMEM);

    proj_kernel<<<dim3(16, 128), 256>>>(x, qw, kw);
    stats_kernel<<<128, 256>>>();
    norm_kernel<<<8704, 256>>>(bnw, bnb);
    attn_kernel<<<dim3(32, 64), 512, ATTN_SMEM>>>(out);
}